// round 4
// baseline (speedup 1.0000x reference)
#include <cuda_runtime.h>
#include <cstdint>

#define BATCH 32
#define CIN   256
#define COUT  256
#define HH_   56
#define WW_   56
#define HW_   (HH_*WW_)
#define NPOS  (BATCH*HW_)

// ---------------- device scratch (no allocs allowed) ----------------
__device__ int8_t g_x8[(size_t)NPOS * CIN];          // [b][h][w][cin] int8 ±1
__device__ int8_t g_w8[(size_t)9 * COUT * CIN];      // [tap][cout][cin] int8 ±1

// ---------------- helpers ----------------
__device__ __forceinline__ uint32_t smem_u32(const void* p) {
    uint32_t a;
    asm("{ .reg .u64 t; cvta.to.shared.u64 t, %1; cvt.u32.u64 %0, t; }" : "=r"(a) : "l"(p));
    return a;
}
__device__ __forceinline__ void cp_async16(uint32_t dst, const void* src, uint32_t sz) {
    asm volatile("cp.async.cg.shared.global [%0], [%1], 16, %2;"
                 :: "r"(dst), "l"(src), "r"(sz) : "memory");
}
#define CP_COMMIT()  asm volatile("cp.async.commit_group;" ::: "memory")
#define CP_WAIT(n)   asm volatile("cp.async.wait_group %0;" :: "n"(n) : "memory")

__device__ __forceinline__ void ldsm4(uint32_t* r, uint32_t addr) {
    asm volatile("ldmatrix.sync.aligned.m8n8.x4.shared.b16 {%0,%1,%2,%3}, [%4];"
                 : "=r"(r[0]), "=r"(r[1]), "=r"(r[2]), "=r"(r[3]) : "r"(addr));
}
__device__ __forceinline__ void mma_s8(int* d, const uint32_t* a, const uint32_t* b) {
    asm volatile(
        "mma.sync.aligned.m16n8k32.row.col.s32.s8.s8.s32 "
        "{%0,%1,%2,%3}, {%4,%5,%6,%7}, {%8,%9}, {%0,%1,%2,%3};"
        : "+r"(d[0]), "+r"(d[1]), "+r"(d[2]), "+r"(d[3])
        : "r"(a[0]), "r"(a[1]), "r"(a[2]), "r"(a[3]), "r"(b[0]), "r"(b[1]));
}

// ---------------- pack x: NCHW f32 -> channels-last int8 ----------------
__global__ void pack_x8_kernel(const float* __restrict__ x) {
    int pos = blockIdx.x * blockDim.x + threadIdx.x;
    if (pos >= NPOS) return;
    int b  = pos / HW_;
    int hw = pos - b * HW_;
    const float* xp = x + (size_t)b * CIN * HW_ + hw;
    int8_t* dst = g_x8 + (size_t)pos * CIN;
    #pragma unroll 4
    for (int k = 0; k < 16; ++k) {          // 16B chunks
        uint32_t v[4];
        #pragma unroll
        for (int q = 0; q < 4; ++q) {
            uint32_t wv = 0;
            #pragma unroll
            for (int j = 0; j < 4; ++j) {
                float f = xp[(size_t)(k * 16 + q * 4 + j) * HW_];
                uint32_t byte = (f >= 0.0f) ? 0x01u : 0xFFu;
                wv |= byte << (8 * j);
            }
            v[q] = wv;
        }
        *(uint4*)(dst + k * 16) = make_uint4(v[0], v[1], v[2], v[3]);
    }
}

// ---------------- pack w: OIHW f32 -> [tap][cout][cin] int8 ----------------
__global__ void pack_w8_kernel(const float* __restrict__ wgt) {
    int idx = blockIdx.x * blockDim.x + threadIdx.x;   // cout*256 + cin
    if (idx >= COUT * CIN) return;
    int cout = idx >> 8, cin = idx & 255;
    const float* wp = wgt + (size_t)idx * 9;
    #pragma unroll
    for (int t = 0; t < 9; ++t)
        g_w8[((size_t)t * COUT + cout) * CIN + cin] = (wp[t] >= 0.0f) ? 1 : -1;
}

// ---------------- conv kernel ----------------
// CTA: M=128 (2 rows x 64 w-slots), N=128 couts. 256 threads = 8 warps (4M x 2N).
#define OFF_WIN   0                      // 4*66*256 = 67584
#define OFF_B     67584                  // 2 x 32768
#define OFF_BIAS  (67584 + 65536)        // 512
#define SMEM_TOTAL (OFF_BIAS + 512)      // 133632

__global__ void __launch_bounds__(256, 1)
bconv_imma_kernel(const float* __restrict__ bias, float* __restrict__ out) {
    extern __shared__ char smem[];
    uint32_t sb = smem_u32(smem);
    const int tid = threadIdx.x;
    const int wid = tid >> 5;
    const int lid = tid & 31;

    const int h0     = blockIdx.x * 2;      // output rows h0, h0+1
    const int b      = blockIdx.y;
    const int ngBase = blockIdx.z * 128;    // cout group

    const int warpM = wid & 3;              // 0..3
    const int warpN = wid >> 2;             // 0..1
    const int sW     = warpM >> 1;          // output row within CTA tile
    const int wpBase = (warpM & 1) * 32;    // w-slot base

    // ---- stage bias ----
    float* bias_s = (float*)(smem + OFF_BIAS);
    if (tid < 128) bias_s[tid] = bias[ngBase + tid];

    // ---- issue window loads: rows h0-1..h0+2, cols -1..64, 256B each ----
    for (int i = tid; i < 4 * 66 * 16; i += 256) {
        int rr = i / 1056;
        int rem = i - rr * 1056;
        int wc = rem >> 4;
        int ch = rem & 15;
        int rin  = h0 + rr - 1;
        int wcol = wc - 1;
        bool valid = (rin >= 0) && (rin < HH_) && (wcol >= 0) && (wcol < WW_);
        const int8_t* src = valid
            ? (g_x8 + ((size_t)((b * HH_ + rin) * WW_ + wcol)) * CIN + ch * 16)
            : g_x8;
        uint32_t dst = sb + OFF_WIN + (uint32_t)(rr * 66 + wc) * 256
                     + (uint32_t)((ch ^ (wc & 7)) << 4);
        cp_async16(dst, src, valid ? 16u : 0u);
    }
    // ---- issue B tap 0 into buf0, commit with window ----
    for (int i = tid; i < 2048; i += 256) {
        int cl = i >> 4, ch = i & 15;
        const int8_t* src = g_w8 + ((size_t)(0 * COUT) + ngBase + cl) * CIN + ch * 16;
        cp_async16(sb + OFF_B + (uint32_t)cl * 256 + (uint32_t)((ch ^ (cl & 7)) << 4), src, 16);
    }
    CP_COMMIT();
    // ---- issue B tap 1 into buf1 ----
    for (int i = tid; i < 2048; i += 256) {
        int cl = i >> 4, ch = i & 15;
        const int8_t* src = g_w8 + ((size_t)(1 * COUT) + ngBase + cl) * CIN + ch * 16;
        cp_async16(sb + OFF_B + 32768u + (uint32_t)cl * 256 + (uint32_t)((ch ^ (cl & 7)) << 4), src, 16);
    }
    CP_COMMIT();
    CP_WAIT(1);            // window + B0 complete
    __syncthreads();

    // ---- per-lane invariants ----
    const int grp   = lid >> 3;        // ldmatrix tile group 0..3
    const int rowIn = lid & 7;
    const int cbitA = grp >> 1;        // A: k-chunk bit
    const int cbitB = grp & 1;         // B: k-chunk bit
    int localA[2];
    localA[0] = ((grp & 1) << 3) + rowIn;          // + mf*16
    localA[1] = 16 + localA[0];
    int clB[4], b7[4];
    #pragma unroll
    for (int p = 0; p < 4; ++p) {
        clB[p] = warpN * 64 + p * 16 + ((grp >> 1) << 3) + rowIn;
        b7[p]  = clB[p] & 7;
    }

    int acc[2][8][4];
    #pragma unroll
    for (int mf = 0; mf < 2; ++mf)
        #pragma unroll
        for (int nf = 0; nf < 8; ++nf)
            #pragma unroll
            for (int q = 0; q < 4; ++q) acc[mf][nf][q] = 0;

    // ---- main loop over 9 taps ----
    for (int t = 0; t < 9; ++t) {
        const int dh = t / 3, dw = t - dh * 3;
        const uint32_t bOff = OFF_B + (uint32_t)(t & 1) * 32768u;

        uint32_t aB[2]; int a7[2];
        #pragma unroll
        for (int mf = 0; mf < 2; ++mf) {
            int wc = wpBase + localA[mf] + dw;
            aB[mf] = sb + OFF_WIN + (uint32_t)(((sW + dh) * 66 + wc) * 256);
            a7[mf] = wc & 7;
        }

        #pragma unroll
        for (int kk = 0; kk < 8; ++kk) {
            uint32_t A[2][4], Bf[4][4];
            #pragma unroll
            for (int mf = 0; mf < 2; ++mf)
                ldsm4(A[mf], aB[mf] + (uint32_t)((((kk << 1) + cbitA) ^ a7[mf]) << 4));
            #pragma unroll
            for (int p = 0; p < 4; ++p)
                ldsm4(Bf[p], sb + bOff + (uint32_t)clB[p] * 256
                            + (uint32_t)((((kk << 1) + cbitB) ^ b7[p]) << 4));
            #pragma unroll
            for (int mf = 0; mf < 2; ++mf)
                #pragma unroll
                for (int p = 0; p < 4; ++p) {
                    mma_s8(acc[mf][2 * p + 0], A[mf], &Bf[p][0]);
                    mma_s8(acc[mf][2 * p + 1], A[mf], &Bf[p][2]);
                }
        }

        __syncthreads();                       // all warps done reading buf[t&1]
        if (t + 2 <= 8) {
            int tn = t + 2;
            uint32_t nOff = OFF_B + (uint32_t)(tn & 1) * 32768u;
            for (int i = tid; i < 2048; i += 256) {
                int cl = i >> 4, ch = i & 15;
                const int8_t* src = g_w8 + ((size_t)(tn * COUT) + ngBase + cl) * CIN + ch * 16;
                cp_async16(sb + nOff + (uint32_t)cl * 256 + (uint32_t)((ch ^ (cl & 7)) << 4), src, 16);
            }
            CP_COMMIT();
        }
        if (t < 8) {
            if (t + 2 <= 8) { CP_WAIT(1); } else { CP_WAIT(0); }
            __syncthreads();                   // B(t+1) visible to all
        }
    }

    // ---- epilogue: transpose accs through smem, coalesced store ----
    int* accS = (int*)smem;   // [128][129] s32, reuses window region (66048 B)
    {
        const int mb = warpM * 32;
        const int nb = warpN * 64;
        #pragma unroll
        for (int mf = 0; mf < 2; ++mf) {
            int r0 = mb + mf * 16 + (lid >> 2);
            #pragma unroll
            for (int nf = 0; nf < 8; ++nf) {
                int c = nb + nf * 8 + (lid & 3) * 2;
                accS[r0 * 129 + c]           = acc[mf][nf][0];
                accS[r0 * 129 + c + 1]       = acc[mf][nf][1];
                accS[(r0 + 8) * 129 + c]     = acc[mf][nf][2];
                accS[(r0 + 8) * 129 + c + 1] = acc[mf][nf][3];
            }
        }
    }
    __syncthreads();
    {
        for (int it = 0; it < 32; ++it) {
            int P = wid * 32 + it;
            int n = P >> 1, s = P & 1;
            float bv = bias_s[n];
            float* rb = out + ((size_t)(b * COUT + ngBase + n) * HH_ + (h0 + s)) * WW_;
            int m = s * 64;
            rb[lid] = (float)accS[(m + lid) * 129 + n] + bv;
            if (lid < WW_ - 32)
                rb[32 + lid] = (float)accS[(m + 32 + lid) * 129 + n] + bv;
        }
    }
}

// ---------------------------------------------------------------------------
extern "C" void kernel_launch(void* const* d_in, const int* in_sizes, int n_in,
                              void* d_out, int out_size) {
    const float* x    = (const float*)d_in[0];
    const float* wgt  = (const float*)d_in[1];
    const float* bias = (const float*)d_in[2];
    float* out = (float*)d_out;

    pack_x8_kernel<<<(NPOS + 255) / 256, 256>>>(x);
    pack_w8_kernel<<<(COUT * CIN + 255) / 256, 256>>>(wgt);

    cudaFuncSetAttribute(bconv_imma_kernel,
                         cudaFuncAttributeMaxDynamicSharedMemorySize, SMEM_TOTAL);
    dim3 grid(HH_ / 2, BATCH, COUT / 128);
    bconv_imma_kernel<<<grid, 256, SMEM_TOTAL>>>(bias, out);
}

// round 5
// speedup vs baseline: 2.4889x; 2.4889x over previous
#include <cuda_runtime.h>
#include <cstdint>

#define BATCH 32
#define CIN   256
#define COUT  256
#define HH_   56
#define WW_   56
#define HW_   (HH_*WW_)
#define NPOS  (BATCH*HW_)

// ---------------- device scratch ----------------
__device__ uint4 g_xpack[NPOS * 2];        // [pos][2]: 8 u32 sign bits (bit=1 iff x>=0)
__device__ uint4 g_wpack[COUT * 9 * 2];    // [cout*9+tap][2]

// ---------------- fused pack kernel (keeps launch count at 2) ----------------
__global__ void pack_all_kernel(const float* __restrict__ x,
                                const float* __restrict__ wgt) {
    if (blockIdx.x < 392) {                       // 392*256 == NPOS exactly
        int pos = blockIdx.x * 256 + threadIdx.x;
        int b  = pos / HW_;
        int hw = pos - b * HW_;
        const float* xp = x + (size_t)b * CIN * HW_ + hw;
        uint32_t wds[8];
        #pragma unroll
        for (int k = 0; k < 8; ++k) {
            uint32_t wd = 0;
            #pragma unroll
            for (int i = 0; i < 32; ++i) {
                float v = xp[(size_t)(k * 32 + i) * HW_];
                wd |= (v >= 0.0f ? 1u : 0u) << i;
            }
            wds[k] = wd;
        }
        g_xpack[pos * 2 + 0] = make_uint4(wds[0], wds[1], wds[2], wds[3]);
        g_xpack[pos * 2 + 1] = make_uint4(wds[4], wds[5], wds[6], wds[7]);
    } else {
        int idx = (blockIdx.x - 392) * 256 + threadIdx.x;   // cout*9+tap
        if (idx >= COUT * 9) return;
        int cout = idx / 9;
        int tap  = idx - cout * 9;
        const float* wp = wgt + (size_t)cout * CIN * 9 + tap;
        uint32_t wds[8];
        #pragma unroll
        for (int k = 0; k < 8; ++k) {
            uint32_t wd = 0;
            #pragma unroll
            for (int i = 0; i < 32; ++i) {
                float v = wp[(size_t)(k * 32 + i) * 9];
                wd |= (v >= 0.0f ? 1u : 0u) << i;
            }
            wds[k] = wd;
        }
        g_wpack[idx * 2 + 0] = make_uint4(wds[0], wds[1], wds[2], wds[3]);
        g_wpack[idx * 2 + 1] = make_uint4(wds[4], wds[5], wds[6], wds[7]);
    }
}

// ---------------- main conv: weights-in-registers, x broadcast, sliding ring --
// Block = 256 threads = 8 warps. Warp w covers couts w*32..w*32+31 (lane=cout).
// Block computes one (b, h) output row for ALL 256 couts, 56 w positions.
__global__ void __launch_bounds__(256, 2)
bconv_pop_kernel(const float* __restrict__ bias, float* __restrict__ out) {
    __shared__ uint4 xs[3 * WW_ * 2];     // [row][v][half]

    const int tid  = threadIdx.x;
    const int lane = tid & 31;
    const int wid  = tid >> 5;
    const int h    = blockIdx.x;
    const int b    = blockIdx.y;
    const int cout = wid * 32 + lane;

    const bool rv0 = (h > 0), rv2 = (h < HH_ - 1);

    // ---- stage x (3 rows x 56 cols x 32B), zero-fill invalid rows ----
    for (int i = tid; i < 3 * WW_ * 2; i += 256) {
        int row = i / (WW_ * 2);
        int rem = i - row * (WW_ * 2);
        int v = rem >> 1, j = rem & 1;
        int rin = h - 1 + row;
        uint4 val = make_uint4(0u, 0u, 0u, 0u);
        if (rin >= 0 && rin < HH_)
            val = g_xpack[((size_t)(b * HH_ + rin) * WW_ + v) * 2 + j];
        xs[(row * WW_ + v) * 2 + j] = val;
    }

    // ---- per-lane weights in registers ----
    uint32_t wreg[9][8];
    #pragma unroll
    for (int t = 0; t < 9; ++t) {
        uint4 a = g_wpack[(cout * 9 + t) * 2 + 0];
        uint4 q = g_wpack[(cout * 9 + t) * 2 + 1];
        wreg[t][0] = a.x; wreg[t][1] = a.y; wreg[t][2] = a.z; wreg[t][3] = a.w;
        wreg[t][4] = q.x; wreg[t][5] = q.y; wreg[t][6] = q.z; wreg[t][7] = q.w;
    }
    const float bv = bias[cout];

    // ---- row-pad correction constants (block-uniform selects) ----
    int pm[3], pl[3], pr[3];
    #pragma unroll
    for (int dh = 0; dh < 3; ++dh) {
        int p0 = 0, p1 = 0, p2 = 0;
        #pragma unroll
        for (int k = 0; k < 8; ++k) {
            p0 += __popc(wreg[dh * 3 + 0][k]);
            p1 += __popc(wreg[dh * 3 + 1][k]);
            p2 += __popc(wreg[dh * 3 + 2][k]);
        }
        pm[dh] = p0 + p1 + p2; pl[dh] = p1 + p2; pr[dh] = p0 + p1;
    }
    const int nrows = (int)rv0 + 1 + (int)rv2;
    const int cmid   = 768 * nrows + 2 * ((rv0 ? 0 : pm[0]) + (rv2 ? 0 : pm[2]));
    const int cleft  = 512 * nrows + 2 * ((rv0 ? 0 : pl[0]) + (rv2 ? 0 : pl[2]));
    const int cright = 512 * nrows + 2 * ((rv0 ? 0 : pr[0]) + (rv2 ? 0 : pr[2]));

    __syncthreads();

    float* obase = out + ((size_t)(b * COUT + cout) * HH_ + h) * WW_;

    int ring[4] = {0, 0, 0, 0};
    float fb[8];

    // v = input column 0..55.  x col v feeds outputs w = v+1-dw, dw in {0,1,2}.
    // Output w completes at end of step v = w+1 (or v=55 for w=55).
    for (int v0 = 0; v0 < 7; ++v0) {
        #pragma unroll
        for (int u = 0; u < 8; ++u) {
            const int v = v0 * 8 + u;   // (v & 7) == u; ring indices compile-time
            int addn = 0, addm = 0, addo = 0;
            #pragma unroll
            for (int row = 0; row < 3; ++row) {
                uint4 xa = xs[(row * WW_ + v) * 2 + 0];
                uint4 xb = xs[(row * WW_ + v) * 2 + 1];
                uint32_t xw[8] = {xa.x, xa.y, xa.z, xa.w, xb.x, xb.y, xb.z, xb.w};
                #pragma unroll
                for (int k = 0; k < 8; ++k) {
                    addn += __popc(xw[k] ^ wreg[row * 3 + 0][k]);
                    addm += __popc(xw[k] ^ wreg[row * 3 + 1][k]);
                    addo += __popc(xw[k] ^ wreg[row * 3 + 2][k]);
                }
            }
            ring[(u + 1) & 3] += addn;      // w = v+1
            ring[u & 3]       += addm;      // w = v
            ring[(u + 3) & 3] += addo;      // w = v-1  (completes now)

            if (u == 0) {
                if (v0 == 0) {
                    ring[3] = 0;            // clear garbage from w=-1
                } else {
                    // w = 8*v0-1 completes into slot 3; then flush group v0-1
                    fb[7] = (float)(cmid - 2 * ring[3]) + bv;
                    ring[3] = 0;
                    float4 o0 = make_float4(fb[0], fb[1], fb[2], fb[3]);
                    float4 o1 = make_float4(fb[4], fb[5], fb[6], fb[7]);
                    *(float4*)(obase + (v0 - 1) * 8)     = o0;
                    *(float4*)(obase + (v0 - 1) * 8 + 4) = o1;
                }
            } else {
                // w = v-1 completes into slot (u+3)&3
                const int slot = (u + 3) & 3;
                int c = cmid;
                if (u == 1) c = (v0 == 0) ? cleft : cmid;   // w==0 edge
                fb[(u - 1) & 7] = (float)(c - 2 * ring[slot]) + bv;
                ring[slot] = 0;
            }
        }
    }
    // tail: w = 55 (edge, ncols=2) sits in slot 55&3 = 3
    fb[7] = (float)(cright - 2 * ring[3]) + bv;
    float4 o0 = make_float4(fb[0], fb[1], fb[2], fb[3]);
    float4 o1 = make_float4(fb[4], fb[5], fb[6], fb[7]);
    *(float4*)(obase + 48) = o0;
    *(float4*)(obase + 52) = o1;
}

// ---------------------------------------------------------------------------
extern "C" void kernel_launch(void* const* d_in, const int* in_sizes, int n_in,
                              void* d_out, int out_size) {
    const float* x    = (const float*)d_in[0];
    const float* wgt  = (const float*)d_in[1];
    const float* bias = (const float*)d_in[2];
    float* out = (float*)d_out;

    pack_all_kernel<<<401, 256>>>(x, wgt);
    dim3 grid(HH_, BATCH);
    bconv_pop_kernel<<<grid, 256>>>(bias, out);
}

// round 6
// speedup vs baseline: 2.5109x; 1.0089x over previous
#include <cuda_runtime.h>
#include <cstdint>

#define BATCH 32
#define CIN   256
#define COUT  256
#define HH_   56
#define WW_   56
#define HW_   (HH_*WW_)
#define NPOS  (BATCH*HW_)

// ---------------- device scratch ----------------
__device__ uint4 g_xpack[NPOS * 2];        // [pos][2]: 8 u32 sign bits (bit=1 iff x>=0)
__device__ uint4 g_wpack[COUT * 9 * 2];    // [cout*9+tap][2]

// ---------------- fused pack kernel ----------------
__global__ void pack_all_kernel(const float* __restrict__ x,
                                const float* __restrict__ wgt) {
    if (blockIdx.x < 392) {                       // 392*256 == NPOS exactly
        int pos = blockIdx.x * 256 + threadIdx.x;
        int b  = pos / HW_;
        int hw = pos - b * HW_;
        const float* xp = x + (size_t)b * CIN * HW_ + hw;
        uint32_t wds[8];
        #pragma unroll
        for (int k = 0; k < 8; ++k) {
            uint32_t wd = 0;
            #pragma unroll
            for (int i = 0; i < 32; ++i) {
                float v = xp[(size_t)(k * 32 + i) * HW_];
                wd |= (v >= 0.0f ? 1u : 0u) << i;
            }
            wds[k] = wd;
        }
        g_xpack[pos * 2 + 0] = make_uint4(wds[0], wds[1], wds[2], wds[3]);
        g_xpack[pos * 2 + 1] = make_uint4(wds[4], wds[5], wds[6], wds[7]);
    } else {
        int idx = (blockIdx.x - 392) * 256 + threadIdx.x;   // cout*9+tap
        if (idx >= COUT * 9) return;
        int cout = idx / 9;
        int tap  = idx - cout * 9;
        const float* wp = wgt + (size_t)cout * CIN * 9 + tap;
        uint32_t wds[8];
        #pragma unroll
        for (int k = 0; k < 8; ++k) {
            uint32_t wd = 0;
            #pragma unroll
            for (int i = 0; i < 32; ++i) {
                float v = wp[(size_t)(k * 32 + i) * 9];
                wd |= (v >= 0.0f ? 1u : 0u) << i;
            }
            wds[k] = wd;
        }
        g_wpack[idx * 2 + 0] = make_uint4(wds[0], wds[1], wds[2], wds[3]);
        g_wpack[idx * 2 + 1] = make_uint4(wds[4], wds[5], wds[6], wds[7]);
    }
}

// ---------------- main conv: cin split across 2 lanes for occupancy ----------
// Block = 256 threads = 8 warps. Warp: lane = half*16 + csub.
//   csub (0..15) -> cout = bz*128 + wid*16 + csub;  half (0..1) -> cin words 4h..4h+3.
// Block computes one (b, h) output row for 128 couts.
__global__ void __launch_bounds__(256, 3)
bconv_pop_kernel(const float* __restrict__ bias, float* __restrict__ out) {
    __shared__ uint4 xs[3 * WW_ * 2];     // [row][v][half]

    const int tid  = threadIdx.x;
    const int lane = tid & 31;
    const int wid  = tid >> 5;
    const int half = lane >> 4;
    const int csub = lane & 15;
    const int h    = blockIdx.x;
    const int b    = blockIdx.y;
    const int cout = blockIdx.z * 128 + wid * 16 + csub;

    const bool rv0 = (h > 0), rv2 = (h < HH_ - 1);

    // ---- stage x (3 rows x 56 cols x 2 halves), zero-fill invalid rows ----
    for (int i = tid; i < 3 * WW_ * 2; i += 256) {
        int row = i / (WW_ * 2);
        int rem = i - row * (WW_ * 2);
        int v = rem >> 1, j = rem & 1;
        int rin = h - 1 + row;
        uint4 val = make_uint4(0u, 0u, 0u, 0u);
        if (rin >= 0 && rin < HH_)
            val = g_xpack[((size_t)(b * HH_ + rin) * WW_ + v) * 2 + j];
        xs[(row * WW_ + v) * 2 + j] = val;
    }

    // ---- per-lane half-weights in registers (36 regs) ----
    uint32_t wreg[9][4];
    #pragma unroll
    for (int t = 0; t < 9; ++t) {
        uint4 a = g_wpack[(cout * 9 + t) * 2 + half];
        wreg[t][0] = a.x; wreg[t][1] = a.y; wreg[t][2] = a.z; wreg[t][3] = a.w;
    }
    const float bv = bias[cout];

    // ---- per-half pad-correction constants (128 channels per half) ----
    int pm[3], pl[3], pr[3];
    #pragma unroll
    for (int dh = 0; dh < 3; ++dh) {
        int p0 = 0, p1 = 0, p2 = 0;
        #pragma unroll
        for (int k = 0; k < 4; ++k) {
            p0 += __popc(wreg[dh * 3 + 0][k]);
            p1 += __popc(wreg[dh * 3 + 1][k]);
            p2 += __popc(wreg[dh * 3 + 2][k]);
        }
        pm[dh] = p0 + p1 + p2; pl[dh] = p1 + p2; pr[dh] = p0 + p1;
    }
    const int nrows = (int)rv0 + 1 + (int)rv2;
    const int cmid   = 384 * nrows + 2 * ((rv0 ? 0 : pm[0]) + (rv2 ? 0 : pm[2]));
    const int cleft  = 256 * nrows + 2 * ((rv0 ? 0 : pl[0]) + (rv2 ? 0 : pl[2]));
    const int cright = 256 * nrows + 2 * ((rv0 ? 0 : pr[0]) + (rv2 ? 0 : pr[2]));

    __syncthreads();

    float* obase = out + ((size_t)(b * COUT + cout) * HH_ + h) * WW_;

    int ring[4] = {0, 0, 0, 0};
    float fb[8];

    // v = input column. x col v feeds outputs w = v+1-dw, dw in {0,1,2}.
    for (int v0 = 0; v0 < 7; ++v0) {
        #pragma unroll
        for (int u = 0; u < 8; ++u) {
            const int v = v0 * 8 + u;
            int addn = 0, addm = 0, addo = 0;
            #pragma unroll
            for (int row = 0; row < 3; ++row) {
                uint4 xa = xs[(row * WW_ + v) * 2 + half];
                uint32_t xw[4] = {xa.x, xa.y, xa.z, xa.w};
                #pragma unroll
                for (int k = 0; k < 4; ++k) {
                    addn += __popc(xw[k] ^ wreg[row * 3 + 0][k]);
                    addm += __popc(xw[k] ^ wreg[row * 3 + 1][k]);
                    addo += __popc(xw[k] ^ wreg[row * 3 + 2][k]);
                }
            }
            ring[(u + 1) & 3] += addn;      // w = v+1
            ring[u & 3]       += addm;      // w = v
            ring[(u + 3) & 3] += addo;      // w = v-1 (completes now)

            if (u == 0) {
                if (v0 == 0) {
                    ring[3] = 0;            // discard w=-1 garbage
                } else {
                    int comb = cmid - 2 * ring[3];
                    comb += __shfl_xor_sync(0xffffffffu, comb, 16);
                    fb[7] = (float)comb + bv;
                    ring[3] = 0;
                    if (half == 0) {
                        *(float4*)(obase + (v0 - 1) * 8)     = make_float4(fb[0], fb[1], fb[2], fb[3]);
                        *(float4*)(obase + (v0 - 1) * 8 + 4) = make_float4(fb[4], fb[5], fb[6], fb[7]);
                    }
                }
            } else {
                const int slot = (u + 3) & 3;
                int c = cmid;
                if (u == 1) c = (v0 == 0) ? cleft : cmid;   // w==0 edge
                int comb = c - 2 * ring[slot];
                comb += __shfl_xor_sync(0xffffffffu, comb, 16);
                fb[(u - 1) & 7] = (float)comb + bv;
                ring[slot] = 0;
            }
        }
    }
    // tail: w = 55 (edge) sits in slot 3
    {
        int comb = cright - 2 * ring[3];
        comb += __shfl_xor_sync(0xffffffffu, comb, 16);
        fb[7] = (float)comb + bv;
    }
    if (half == 0) {
        *(float4*)(obase + 48) = make_float4(fb[0], fb[1], fb[2], fb[3]);
        *(float4*)(obase + 52) = make_float4(fb[4], fb[5], fb[6], fb[7]);
    }
}

// ---------------------------------------------------------------------------
extern "C" void kernel_launch(void* const* d_in, const int* in_sizes, int n_in,
                              void* d_out, int out_size) {
    const float* x    = (const float*)d_in[0];
    const float* wgt  = (const float*)d_in[1];
    const float* bias = (const float*)d_in[2];
    float* out = (float*)d_out;

    pack_all_kernel<<<401, 256>>>(x, wgt);
    dim3 grid(HH_, BATCH, 2);
    bconv_pop_kernel<<<grid, 256>>>(bias, out);
}

// round 7
// speedup vs baseline: 2.5193x; 1.0034x over previous
#include <cuda_runtime.h>
#include <cstdint>

#define BATCH 32
#define CIN   256
#define COUT  256
#define HH_   56
#define WW_   56
#define HW_   (HH_*WW_)
#define NPOS  (BATCH*HW_)

// ---------------- device scratch ----------------
__device__ uint4 g_xpack[NPOS * 2];        // [pos][2]: 8 u32 sign bits (bit=1 iff x>=0)
__device__ uint4 g_wpack[COUT * 9 * 2];    // [cout*9+tap][2]

// ---------------- fused pack kernel ----------------
__global__ void pack_all_kernel(const float* __restrict__ x,
                                const float* __restrict__ wgt) {
    if (blockIdx.x < 392) {                       // 392*256 == NPOS exactly
        int pos = blockIdx.x * 256 + threadIdx.x;
        int b  = pos / HW_;
        int hw = pos - b * HW_;
        const float* xp = x + (size_t)b * CIN * HW_ + hw;
        uint32_t wds[8];
        #pragma unroll
        for (int k = 0; k < 8; ++k) {
            uint32_t wd = 0;
            #pragma unroll
            for (int i = 0; i < 32; ++i) {
                float v = xp[(size_t)(k * 32 + i) * HW_];
                wd |= (v >= 0.0f ? 1u : 0u) << i;
            }
            wds[k] = wd;
        }
        g_xpack[pos * 2 + 0] = make_uint4(wds[0], wds[1], wds[2], wds[3]);
        g_xpack[pos * 2 + 1] = make_uint4(wds[4], wds[5], wds[6], wds[7]);
    } else {
        int idx = (blockIdx.x - 392) * 256 + threadIdx.x;   // cout*9+tap
        if (idx >= COUT * 9) return;
        int cout = idx / 9;
        int tap  = idx - cout * 9;
        const float* wp = wgt + (size_t)cout * CIN * 9 + tap;
        uint32_t wds[8];
        #pragma unroll
        for (int k = 0; k < 8; ++k) {
            uint32_t wd = 0;
            #pragma unroll
            for (int i = 0; i < 32; ++i) {
                float v = wp[(size_t)(k * 32 + i) * 9];
                wd |= (v >= 0.0f ? 1u : 0u) << i;
            }
            wds[k] = wd;
        }
        g_wpack[idx * 2 + 0] = make_uint4(wds[0], wds[1], wds[2], wds[3]);
        g_wpack[idx * 2 + 1] = make_uint4(wds[4], wds[5], wds[6], wds[7]);
    }
}

// forced IMAD accumulate (fma pipe): acc += p * one
#define MADD(acc, p, one) \
    asm("mad.lo.s32 %0, %1, %2, %0;" : "+r"(acc) : "r"(p), "r"(one))

// ---------------- main conv: cin split across 2 lanes, adds on fma pipe ------
__global__ void __launch_bounds__(256, 3)
bconv_pop_kernel(const float* __restrict__ bias, float* __restrict__ out) {
    __shared__ uint4 xs[3 * WW_ * 2];     // [row][v][half]

    const int tid  = threadIdx.x;
    const int lane = tid & 31;
    const int wid  = tid >> 5;
    const int half = lane >> 4;
    const int csub = lane & 15;
    const int h    = blockIdx.x;
    const int b    = blockIdx.y;
    const int cout = blockIdx.z * 128 + wid * 16 + csub;

    const bool rv0 = (h > 0), rv2 = (h < HH_ - 1);

    int one;
    asm("mov.s32 %0, 1;" : "=r"(one));    // opaque 1 to pin IMAD on fma pipe

    // ---- stage x (3 rows x 56 cols x 2 halves), zero-fill invalid rows ----
    for (int i = tid; i < 3 * WW_ * 2; i += 256) {
        int row = i / (WW_ * 2);
        int rem = i - row * (WW_ * 2);
        int v = rem >> 1, j = rem & 1;
        int rin = h - 1 + row;
        uint4 val = make_uint4(0u, 0u, 0u, 0u);
        if (rin >= 0 && rin < HH_)
            val = g_xpack[((size_t)(b * HH_ + rin) * WW_ + v) * 2 + j];
        xs[(row * WW_ + v) * 2 + j] = val;
    }

    // ---- per-lane half-weights in registers (36 regs) ----
    uint32_t wreg[9][4];
    #pragma unroll
    for (int t = 0; t < 9; ++t) {
        uint4 a = g_wpack[(cout * 9 + t) * 2 + half];
        wreg[t][0] = a.x; wreg[t][1] = a.y; wreg[t][2] = a.z; wreg[t][3] = a.w;
    }
    const float bv = bias[cout];

    // ---- per-half pad-correction constants ----
    int pm[3], pl[3], pr[3];
    #pragma unroll
    for (int dh = 0; dh < 3; ++dh) {
        int p0 = 0, p1 = 0, p2 = 0;
        #pragma unroll
        for (int k = 0; k < 4; ++k) {
            p0 += __popc(wreg[dh * 3 + 0][k]);
            p1 += __popc(wreg[dh * 3 + 1][k]);
            p2 += __popc(wreg[dh * 3 + 2][k]);
        }
        pm[dh] = p0 + p1 + p2; pl[dh] = p1 + p2; pr[dh] = p0 + p1;
    }
    const int nrows = (int)rv0 + 1 + (int)rv2;
    const int cmid   = 384 * nrows + 2 * ((rv0 ? 0 : pm[0]) + (rv2 ? 0 : pm[2]));
    const int cleft  = 256 * nrows + 2 * ((rv0 ? 0 : pl[0]) + (rv2 ? 0 : pl[2]));
    const int cright = 256 * nrows + 2 * ((rv0 ? 0 : pr[0]) + (rv2 ? 0 : pr[2]));

    __syncthreads();

    float* obase = out + ((size_t)(b * COUT + cout) * HH_ + h) * WW_;

    int ring[4] = {0, 0, 0, 0};
    float fb[8];

    for (int v0 = 0; v0 < 7; ++v0) {
        #pragma unroll
        for (int u = 0; u < 8; ++u) {
            const int v = v0 * 8 + u;
            int addn = 0, addm = 0, addo = 0;
            #pragma unroll
            for (int row = 0; row < 3; ++row) {
                uint4 xa = xs[(row * WW_ + v) * 2 + half];
                uint32_t xw[4] = {xa.x, xa.y, xa.z, xa.w};
                #pragma unroll
                for (int k = 0; k < 4; ++k) {
                    int p0 = __popc(xw[k] ^ wreg[row * 3 + 0][k]);
                    int p1 = __popc(xw[k] ^ wreg[row * 3 + 1][k]);
                    int p2 = __popc(xw[k] ^ wreg[row * 3 + 2][k]);
                    MADD(addn, p0, one);
                    MADD(addm, p1, one);
                    MADD(addo, p2, one);
                }
            }
            MADD(ring[(u + 1) & 3], addn, one);   // w = v+1
            MADD(ring[u & 3],       addm, one);   // w = v
            MADD(ring[(u + 3) & 3], addo, one);   // w = v-1 (completes now)

            if (u == 0) {
                if (v0 == 0) {
                    ring[3] = 0;            // discard w=-1 garbage
                } else {
                    int comb = cmid - 2 * ring[3];
                    comb += __shfl_xor_sync(0xffffffffu, comb, 16);
                    fb[7] = (float)comb + bv;
                    ring[3] = 0;
                    if (half == 0) {
                        *(float4*)(obase + (v0 - 1) * 8)     = make_float4(fb[0], fb[1], fb[2], fb[3]);
                        *(float4*)(obase + (v0 - 1) * 8 + 4) = make_float4(fb[4], fb[5], fb[6], fb[7]);
                    }
                }
            } else {
                const int slot = (u + 3) & 3;
                int c = cmid;
                if (u == 1) c = (v0 == 0) ? cleft : cmid;   // w==0 edge
                int comb = c - 2 * ring[slot];
                comb += __shfl_xor_sync(0xffffffffu, comb, 16);
                fb[(u - 1) & 7] = (float)comb + bv;
                ring[slot] = 0;
            }
        }
    }
    // tail: w = 55 (edge) sits in slot 3
    {
        int comb = cright - 2 * ring[3];
        comb += __shfl_xor_sync(0xffffffffu, comb, 16);
        fb[7] = (float)comb + bv;
    }
    if (half == 0) {
        *(float4*)(obase + 48) = make_float4(fb[0], fb[1], fb[2], fb[3]);
        *(float4*)(obase + 52) = make_float4(fb[4], fb[5], fb[6], fb[7]);
    }
}

// ---------------------------------------------------------------------------
extern "C" void kernel_launch(void* const* d_in, const int* in_sizes, int n_in,
                              void* d_out, int out_size) {
    const float* x    = (const float*)d_in[0];
    const float* wgt  = (const float*)d_in[1];
    const float* bias = (const float*)d_in[2];
    float* out = (float*)d_out;

    pack_all_kernel<<<401, 256>>>(x, wgt);
    dim3 grid(HH_, BATCH, 2);
    bconv_pop_kernel<<<grid, 256>>>(bias, out);
}